// round 4
// baseline (speedup 1.0000x reference)
#include <cuda_runtime.h>
#include <cstdint>

#define NN 50000
#define NE 500000
#define DIM 160
#define BOND 14
#define WS 88   // padded k-stride (bf16 elems) -> conflict-free ldmatrix

// ---------------- scratch ----------------
__device__ int   g_is64;
__device__ int   g_src[NE];
__device__ int   g_dst[NE];
__device__ float g_P [NN * DIM];
__device__ float g_H0[NE * DIM];
__device__ float g_H1[NE * DIM];
__device__ float g_S0[NN * DIM];
__device__ float g_S1[NN * DIM];
__device__ float g_M1[NN * DIM];
__device__ unsigned short g_Wih[160 * 174], g_Wil[160 * 174];
__device__ unsigned short g_Whh[160 * 160], g_Whl[160 * 160];
__device__ unsigned short g_Woh[160 * 320], g_Wol[160 * 320];

// ---------------- helpers ----------------
__device__ __forceinline__ uint32_t cvta_s(const void* p) {
    uint32_t r;
    asm("{ .reg .u64 t; cvta.to.shared.u64 t, %1; cvt.u32.u64 %0, t; }" : "=r"(r) : "l"(p));
    return r;
}
__device__ __forceinline__ void ldsm4(uint32_t (&r)[4], uint32_t addr) {
    asm volatile("ldmatrix.sync.aligned.m8n8.x4.shared.b16 {%0,%1,%2,%3}, [%4];"
                 : "=r"(r[0]), "=r"(r[1]), "=r"(r[2]), "=r"(r[3]) : "r"(addr));
}
__device__ __forceinline__ void mma16816(float* c, const uint32_t (&a)[4],
                                         uint32_t b0, uint32_t b1) {
    asm volatile("mma.sync.aligned.m16n8k16.row.col.f32.bf16.bf16.f32 "
                 "{%0,%1,%2,%3},{%4,%5,%6,%7},{%8,%9},{%0,%1,%2,%3};"
                 : "+f"(c[0]), "+f"(c[1]), "+f"(c[2]), "+f"(c[3])
                 : "r"(a[0]), "r"(a[1]), "r"(a[2]), "r"(a[3]), "r"(b0), "r"(b1));
}
__device__ __forceinline__ void split2(float x, float y, uint32_t& hi2, uint32_t& lo2) {
    uint32_t ux = __float_as_uint(x), uy = __float_as_uint(y);
    hi2 = __byte_perm(ux, uy, 0x7632);
    float lx = x - __uint_as_float(ux & 0xffff0000u);
    float ly = y - __uint_as_float(uy & 0xffff0000u);
    asm("cvt.rn.bf16x2.f32 %0, %1, %2;" : "=r"(lo2) : "f"(ly), "f"(lx));
}

// ---------------- index detect/convert ----------------
__global__ void k_detect(const void* ei) {
    if (threadIdx.x == 0 && blockIdx.x == 0) {
        const unsigned long long* p = (const unsigned long long*)ei;
        int ok = 1;
        for (int i = 0; i < 1024; i++)
            if (p[i] >= (unsigned long long)NN) { ok = 0; break; }
        g_is64 = ok;
    }
}
__global__ void k_convert(const void* ei) {
    int i = blockIdx.x * blockDim.x + threadIdx.x;
    if (i >= NE) return;
    if (g_is64) {
        const long long* p = (const long long*)ei;
        g_src[i] = (int)p[i];
        g_dst[i] = (int)p[NE + i];
    } else {
        const int* p = (const int*)ei;
        g_src[i] = p[i];
        g_dst[i] = p[NE + i];
    }
}

// ---------------- weight split ----------------
__global__ void k_wsplit(const float* __restrict__ w, unsigned short* __restrict__ hi,
                         unsigned short* __restrict__ lo, int n) {
    int i = blockIdx.x * blockDim.x + threadIdx.x;
    if (i >= n) return;
    float f = w[i];
    uint32_t u = __float_as_uint(f);
    hi[i] = (unsigned short)(u >> 16);
    float lf = f - __uint_as_float(u & 0xffff0000u);
    unsigned short ls;
    asm("cvt.rn.bf16.f32 %0, %1;" : "=h"(ls) : "f"(lf));
    lo[i] = ls;
}

// ---------------- tensor-core GEMM ----------------
// C[M,160] = (sum_ph A_ph[M,klen] @ W[:,wk:wk+klen]^T); epilogue:
//   v = acc (+bias) (+addGather[gIdx[row]]) (+addSeq[row]); relu?; Cout?; red.v4 -> Mred[dstIdx[row]]?
// fuseSub: A := fS[fsrc[row]] - fHp[row^1]  (klen=160)
#define OFF_WHI 0
#define OFF_WLO (160 * WS * 2)
#define OFF_AHI (2 * 160 * WS * 2)
#define OFF_ALO (2 * 160 * WS * 2 + 128 * WS * 2)
#define MMA_SMEM (2 * 160 * WS * 2 + 2 * 128 * WS * 2)   // 101376 B

__global__ __launch_bounds__(256, 2) void k_mma(
    const float* __restrict__ A0, int lda0, int klen0, int wk0,
    const float* __restrict__ A1, int lda1, int klen1, int wk1,
    int nph, int M,
    const unsigned short* __restrict__ Whi, const unsigned short* __restrict__ Wlo, int ldw,
    const float* __restrict__ bias, int dorelu,
    float* __restrict__ Cout,
    float* __restrict__ Mred, const int* __restrict__ dstIdx,
    const float* __restrict__ addGather, const int* __restrict__ gIdx,
    const float* __restrict__ addSeq,
    int fuseSub, const float* __restrict__ fS, const int* __restrict__ fsrc,
    const float* __restrict__ fHp)
{
    extern __shared__ char smem[];
    unsigned short* Whi_s = (unsigned short*)(smem + OFF_WHI);
    unsigned short* Wlo_s = (unsigned short*)(smem + OFF_WLO);
    unsigned short* Ahi_s = (unsigned short*)(smem + OFF_AHI);
    unsigned short* Alo_s = (unsigned short*)(smem + OFF_ALO);
    const uint32_t sbase = cvta_s(smem);

    const int tid = threadIdx.x;
    const int lane = tid & 31, wid = tid >> 5;
    const int warp_m = wid & 3, warp_n = wid >> 2;
    const int m0w = warp_m * 32, n0w = warp_n * 80;
    const int row0 = blockIdx.x * 128;

    const int arow = (lane & 7) + ((lane >> 3) & 1) * 8;
    const int acol = (lane >> 4) * 8;
    const uint32_t aoff = (uint32_t)((m0w + arow) * WS + acol) * 2;
    const uint32_t aAhi = sbase + OFF_AHI + aoff;
    const uint32_t aAlo = sbase + OFF_ALO + aoff;
    const int brow = (lane & 7) + ((lane >> 4) << 3);
    const int bcol = ((lane >> 3) & 1) * 8;
    const uint32_t boff = (uint32_t)((n0w + brow) * WS + bcol) * 2;
    const uint32_t bWhi = sbase + OFF_WHI + boff;
    const uint32_t bWlo = sbase + OFF_WLO + boff;

    float acc[20][4];
#pragma unroll
    for (int t = 0; t < 20; t++)
#pragma unroll
        for (int j = 0; j < 4; j++) acc[t][j] = 0.f;

    for (int ph = 0; ph < nph; ph++) {
        const float* A = (ph == 0) ? A0 : A1;
        const int lda  = (ph == 0) ? lda0 : lda1;
        const int klen = (ph == 0) ? klen0 : klen1;
        const int wk   = (ph == 0) ? wk0 : wk1;
        const int nch = (klen + 79) / 80;

        for (int c = 0; c < nch; c++) {
            const int k0g = c * 80;
            const int kc = min(80, klen - k0g);
            __syncthreads();

            // ---- W chunk ----
            if (kc == 80) {
                for (int idx = tid; idx < 160 * 40; idx += 256) {
                    int h = idx / 40, q = idx - h * 40;
                    int gi = (h * ldw + wk + k0g) >> 1;
                    *(uint32_t*)&Whi_s[h * WS + q * 2] = ((const uint32_t*)Whi)[gi + q];
                    *(uint32_t*)&Wlo_s[h * WS + q * 2] = ((const uint32_t*)Wlo)[gi + q];
                }
            } else {
                for (int idx = tid; idx < 160 * 80; idx += 256) {
                    int h = idx / 80, kk = idx - h * 80;
                    unsigned short vh = 0, vl = 0;
                    if (kk < kc) {
                        int gi = h * ldw + wk + k0g + kk;
                        vh = Whi[gi]; vl = Wlo[gi];
                    }
                    Whi_s[h * WS + kk] = vh;
                    Wlo_s[h * WS + kk] = vl;
                }
            }

            // ---- A chunk ----
            if (fuseSub) {
                for (int idx = tid; idx < 128 * 20; idx += 256) {
                    int r = idx / 20, q = idx - r * 20;
                    int row = row0 + r;
                    float4 v = make_float4(0.f, 0.f, 0.f, 0.f);
                    if (row < M) {
                        int q4 = c * 20 + q;
                        float4 s = reinterpret_cast<const float4*>(fS + (size_t)fsrc[row] * DIM)[q4];
                        float4 h = reinterpret_cast<const float4*>(fHp + (size_t)(row ^ 1) * DIM)[q4];
                        v.x = s.x - h.x; v.y = s.y - h.y; v.z = s.z - h.z; v.w = s.w - h.w;
                    }
                    uint32_t h2a, l2a, h2b, l2b;
                    split2(v.x, v.y, h2a, l2a);
                    split2(v.z, v.w, h2b, l2b);
                    uint32_t* dh = (uint32_t*)&Ahi_s[r * WS + q * 4];
                    uint32_t* dl = (uint32_t*)&Alo_s[r * WS + q * 4];
                    dh[0] = h2a; dh[1] = h2b;
                    dl[0] = l2a; dl[1] = l2b;
                }
            } else if (kc == 80 && (lda & 3) == 0) {
                for (int idx = tid; idx < 128 * 20; idx += 256) {
                    int r = idx / 20, q = idx - r * 20;
                    int row = row0 + r;
                    float4 v = make_float4(0.f, 0.f, 0.f, 0.f);
                    if (row < M)
                        v = *reinterpret_cast<const float4*>(A + (size_t)row * lda + k0g + q * 4);
                    uint32_t h2a, l2a, h2b, l2b;
                    split2(v.x, v.y, h2a, l2a);
                    split2(v.z, v.w, h2b, l2b);
                    uint32_t* dh = (uint32_t*)&Ahi_s[r * WS + q * 4];
                    uint32_t* dl = (uint32_t*)&Alo_s[r * WS + q * 4];
                    dh[0] = h2a; dh[1] = h2b;
                    dl[0] = l2a; dl[1] = l2b;
                }
            } else {
                for (int idx = tid; idx < 128 * 80; idx += 256) {
                    int r = idx / 80, kk = idx - r * 80;
                    int row = row0 + r;
                    float f = 0.f;
                    if (row < M && kk < kc) f = A[(size_t)row * lda + k0g + kk];
                    uint32_t u = __float_as_uint(f);
                    Ahi_s[r * WS + kk] = (unsigned short)(u >> 16);
                    float lf = f - __uint_as_float(u & 0xffff0000u);
                    unsigned short ls;
                    asm("cvt.rn.bf16.f32 %0, %1;" : "=h"(ls) : "f"(lf));
                    Alo_s[r * WS + kk] = ls;
                }
            }
            __syncthreads();

            // ---- mma ----
            const int ksteps = (kc + 15) >> 4;
            for (int ks = 0; ks < ksteps; ks++) {
                const uint32_t ko = (uint32_t)ks * 32;
                uint32_t ah0[4], ah1[4], al0[4], al1[4];
                ldsm4(ah0, aAhi + ko);
                ldsm4(ah1, aAhi + ko + 16 * WS * 2);
                ldsm4(al0, aAlo + ko);
                ldsm4(al1, aAlo + ko + 16 * WS * 2);
#pragma unroll
                for (int p = 0; p < 5; p++) {
                    const uint32_t bo = ko + (uint32_t)p * (16 * WS * 2);
                    uint32_t bh[4], bl[4];
                    ldsm4(bh, bWhi + bo);
                    ldsm4(bl, bWlo + bo);
                    mma16816(acc[2 * p],      ah0, bh[0], bh[1]);
                    mma16816(acc[2 * p],      ah0, bl[0], bl[1]);
                    mma16816(acc[2 * p],      al0, bh[0], bh[1]);
                    mma16816(acc[2 * p + 1],  ah0, bh[2], bh[3]);
                    mma16816(acc[2 * p + 1],  ah0, bl[2], bl[3]);
                    mma16816(acc[2 * p + 1],  al0, bh[2], bh[3]);
                    mma16816(acc[10 + 2 * p],     ah1, bh[0], bh[1]);
                    mma16816(acc[10 + 2 * p],     ah1, bl[0], bl[1]);
                    mma16816(acc[10 + 2 * p],     al1, bh[0], bh[1]);
                    mma16816(acc[10 + 2 * p + 1], ah1, bh[2], bh[3]);
                    mma16816(acc[10 + 2 * p + 1], ah1, bl[2], bl[3]);
                    mma16816(acc[10 + 2 * p + 1], al1, bh[2], bh[3]);
                }
            }
        }
    }

    // ---- epilogue: stage fragments through smem (overlay operand buffers) ----
    __syncthreads();
    float* Cs = (float*)smem;   // stride 164 floats per row
    const int rfrag = m0w + (lane >> 2);
    const int cfrag = n0w + (lane & 3) * 2;
#pragma unroll
    for (int mt = 0; mt < 2; mt++)
#pragma unroll
        for (int half = 0; half < 2; half++) {
            int r = rfrag + mt * 16 + half * 8;
#pragma unroll
            for (int nt = 0; nt < 10; nt++) {
                float* p = &Cs[r * 164 + cfrag + nt * 8];
                p[0] = acc[mt * 10 + nt][half * 2 + 0];
                p[1] = acc[mt * 10 + nt][half * 2 + 1];
            }
        }
    __syncthreads();

    for (int idx = tid; idx < 128 * 40; idx += 256) {
        int r = idx / 40, q = idx - r * 40;
        int row = row0 + r;
        if (row >= M) continue;
        float4 v = *reinterpret_cast<float4*>(&Cs[r * 164 + q * 4]);
        if (bias) {
            float4 b = reinterpret_cast<const float4*>(bias)[q];
            v.x += b.x; v.y += b.y; v.z += b.z; v.w += b.w;
        }
        if (addGather) {
            float4 g = reinterpret_cast<const float4*>(addGather + (size_t)gIdx[row] * DIM)[q];
            v.x += g.x; v.y += g.y; v.z += g.z; v.w += g.w;
        }
        if (addSeq) {
            float4 g = reinterpret_cast<const float4*>(addSeq + (size_t)row * DIM)[q];
            v.x += g.x; v.y += g.y; v.z += g.z; v.w += g.w;
        }
        if (dorelu) {
            v.x = fmaxf(v.x, 0.f); v.y = fmaxf(v.y, 0.f);
            v.z = fmaxf(v.z, 0.f); v.w = fmaxf(v.w, 0.f);
        }
        if (Cout)
            reinterpret_cast<float4*>(Cout + (size_t)row * DIM)[q] = v;
        if (Mred) {
            float* p = Mred + (size_t)dstIdx[row] * DIM + q * 4;
            asm volatile("red.global.add.v4.f32 [%0], {%1,%2,%3,%4};"
                         :: "l"(p), "f"(v.x), "f"(v.y), "f"(v.z), "f"(v.w) : "memory");
        }
    }
}

// ---------------- where(rowsum==0, x, M) ----------------
__global__ void k_where(float* __restrict__ M, const float* __restrict__ x)
{
    int gt = blockIdx.x * blockDim.x + threadIdx.x;
    int n = gt >> 5;
    int lane = gt & 31;
    if (n >= NN) return;
    float s = 0.f;
#pragma unroll
    for (int j = 0; j < 5; j++) s += M[n * DIM + lane + j * 32];
#pragma unroll
    for (int o = 16; o; o >>= 1) s += __shfl_xor_sync(0xffffffffu, s, o);
    if (s == 0.f) {
#pragma unroll
        for (int j = 0; j < 5; j++)
            M[n * DIM + lane + j * 32] = x[n * DIM + lane + j * 32];
    }
}

// ---------------- launch ----------------
extern "C" void kernel_launch(void* const* d_in, const int* in_sizes, int n_in,
                              void* d_out, int out_size)
{
    const float* x    = (const float*)d_in[0];
    const float* ea   = (const float*)d_in[1];
    const void*  eidx = d_in[2];
    const float* Wi_w = (const float*)d_in[4];
    const float* Wi_b = (const float*)d_in[5];
    const float* Wh_w = (const float*)d_in[6];
    const float* Wh_b = (const float*)d_in[7];
    const float* Wo_w = (const float*)d_in[8];
    const float* Wo_b = (const float*)d_in[9];
    float* out = (float*)d_out;

    void *pP, *pH0, *pH1, *pS0, *pS1, *pM1, *pSrc, *pDst;
    void *pWih, *pWil, *pWhh, *pWhl, *pWoh, *pWol;
    cudaGetSymbolAddress(&pP,  g_P);
    cudaGetSymbolAddress(&pH0, g_H0);
    cudaGetSymbolAddress(&pH1, g_H1);
    cudaGetSymbolAddress(&pS0, g_S0);
    cudaGetSymbolAddress(&pS1, g_S1);
    cudaGetSymbolAddress(&pM1, g_M1);
    cudaGetSymbolAddress(&pSrc, g_src);
    cudaGetSymbolAddress(&pDst, g_dst);
    cudaGetSymbolAddress(&pWih, g_Wih);
    cudaGetSymbolAddress(&pWil, g_Wil);
    cudaGetSymbolAddress(&pWhh, g_Whh);
    cudaGetSymbolAddress(&pWhl, g_Whl);
    cudaGetSymbolAddress(&pWoh, g_Woh);
    cudaGetSymbolAddress(&pWol, g_Wol);

    cudaFuncSetAttribute(k_mma, cudaFuncAttributeMaxDynamicSharedMemorySize, MMA_SMEM);

    const int gridE = (NE + 127) / 128;
    const int gridN = (NN + 127) / 128;
    const int gridC = (NE + 255) / 256;
    const int gridW = (NN * 32) / 256;

    k_detect<<<1, 32>>>(eidx);
    k_convert<<<gridC, 256>>>(eidx);

    k_wsplit<<<(160 * 174 + 255) / 256, 256>>>(Wi_w, (unsigned short*)pWih, (unsigned short*)pWil, 160 * 174);
    k_wsplit<<<(160 * 160 + 255) / 256, 256>>>(Wh_w, (unsigned short*)pWhh, (unsigned short*)pWhl, 160 * 160);
    k_wsplit<<<(160 * 320 + 255) / 256, 256>>>(Wo_w, (unsigned short*)pWoh, (unsigned short*)pWol, 160 * 320);

    // P = x @ Wi_x^T + Wi_b
    k_mma<<<gridN, 256, MMA_SMEM>>>(x, DIM, DIM, 0, nullptr, 0, 0, 0, 1, NN,
                                    (const unsigned short*)pWih, (const unsigned short*)pWil, DIM + BOND,
                                    Wi_b, 0, (float*)pP,
                                    nullptr, nullptr, nullptr, nullptr, nullptr,
                                    0, nullptr, nullptr, nullptr);

    // H0 = relu(ea @ Wi_e^T + P[src]);  S0 = seg_dst(H0)
    cudaMemsetAsync(pS0, 0, (size_t)NN * DIM * sizeof(float));
    k_mma<<<gridE, 256, MMA_SMEM>>>(ea, BOND, BOND, DIM, nullptr, 0, 0, 0, 1, NE,
                                    (const unsigned short*)pWih, (const unsigned short*)pWil, DIM + BOND,
                                    nullptr, 1, (float*)pH0,
                                    (float*)pS0, (const int*)pDst,
                                    (const float*)pP, (const int*)pSrc, nullptr,
                                    0, nullptr, nullptr, nullptr);

    // iter1: H1 = relu(H0 + (S0[src]-H0[rev]) @ Wh^T + b);  S1 = seg_dst(H1)
    cudaMemsetAsync(pS1, 0, (size_t)NN * DIM * sizeof(float));
    k_mma<<<gridE, 256, MMA_SMEM>>>(nullptr, DIM, DIM, 0, nullptr, 0, 0, 0, 1, NE,
                                    (const unsigned short*)pWhh, (const unsigned short*)pWhl, DIM,
                                    Wh_b, 1, (float*)pH1,
                                    (float*)pS1, (const int*)pDst,
                                    nullptr, nullptr, (const float*)pH0,
                                    1, (const float*)pS0, (const int*)pSrc, (const float*)pH0);

    // iter2: H2 = relu(H0 + (S1[src]-H1[rev]) @ Wh^T + b);  M1 = seg_dst(H2)  (H2 not stored)
    cudaMemsetAsync(pM1, 0, (size_t)NN * DIM * sizeof(float));
    k_mma<<<gridE, 256, MMA_SMEM>>>(nullptr, DIM, DIM, 0, nullptr, 0, 0, 0, 1, NE,
                                    (const unsigned short*)pWhh, (const unsigned short*)pWhl, DIM,
                                    Wh_b, 1, nullptr,
                                    (float*)pM1, (const int*)pDst,
                                    nullptr, nullptr, (const float*)pH0,
                                    1, (const float*)pS1, (const int*)pSrc, (const float*)pH1);

    k_where<<<gridW, 256>>>((float*)pM1, x);

    // out = relu([x ; M1] @ Wo^T + Wo_b)
    k_mma<<<gridN, 256, MMA_SMEM>>>(x, DIM, DIM, 0, (const float*)pM1, DIM, DIM, DIM, 2, NN,
                                    (const unsigned short*)pWoh, (const unsigned short*)pWol, 2 * DIM,
                                    Wo_b, 1, out,
                                    nullptr, nullptr, nullptr, nullptr, nullptr,
                                    0, nullptr, nullptr, nullptr);
}